// round 14
// baseline (speedup 1.0000x reference)
#include <cuda_runtime.h>
#include <cuda_bf16.h>
#include <math.h>
#include <stdint.h>

#define B_   256
#define D_   256
#define H_   8
#define HD_  32
#define FF_  1024
#define M_   2048
#define SCALE_ 0.17677669529663687f   /* 1/sqrt(32) */
#define THR_ 0.5f
#define MOM_ 0.9f
#define LR_  0.1f
#define NSPLIT_ 16
#define KSPLIT_ (M_ / NSPLIT_)   /* 128 keys per split */
#define FSPLIT_ 16               /* FFN2 split-K */
#define NPC_ 64                  /* psum partial columns */
#define STG_ 4                   /* cp.async pipeline stages */

// ---------------- scratch (device globals) -----------------------------------
__device__ float g_proj_src[B_ * 3 * D_];
__device__ float g_kv_mem[M_ * 2 * D_];
__device__ __nv_bfloat16 g_logits[H_ * B_ * M_];   // UNNORMALIZED exp(logit*scale), bf16
__device__ float g_psum[NPC_ * H_ * B_];
__device__ float g_pself[H_ * B_];
__device__ float g_sinv[H_ * B_];
__device__ float g_ctx_part[NSPLIT_ * B_ * D_];
__device__ float g_attn_part[4 * B_ * D_];
__device__ float g_ff_part[FSPLIT_ * B_ * D_];
__device__ float g_src_norm[B_];
__device__ float g_mem_norm[M_];
__device__ int   g_flag;
__device__ int   g_max_bits[B_];
__device__ float g_ctx[B_ * D_];
__device__ float g_h[B_ * D_];
__device__ float g_hidden[B_ * FF_];
__device__ int   g_row_src[M_];
__device__ float g_upd_s[B_];

__device__ __forceinline__ uint32_t f2tf32(float f) {
    uint32_t r;
    asm("cvt.rna.tf32.f32 %0, %1;" : "=r"(r) : "f"(f));
    return r;
}
__device__ __forceinline__ void mma_tf32(float c[4], const uint32_t a[4], const uint32_t b[2]) {
    asm volatile(
        "mma.sync.aligned.m16n8k8.row.col.f32.tf32.tf32.f32 "
        "{%0,%1,%2,%3}, {%4,%5,%6,%7}, {%8,%9}, {%0,%1,%2,%3};"
        : "+f"(c[0]), "+f"(c[1]), "+f"(c[2]), "+f"(c[3])
        : "r"(a[0]), "r"(a[1]), "r"(a[2]), "r"(a[3]), "r"(b[0]), "r"(b[1]));
}
__device__ __forceinline__ void cp16(uint32_t saddr, const float* g) {
    asm volatile("cp.async.cg.shared.global [%0], [%1], 16;" :: "r"(saddr), "l"(g));
}
__device__ __forceinline__ int   fenc(float f) { int i = __float_as_int(f); return i >= 0 ? i : (i ^ 0x7FFFFFFF); }
__device__ __forceinline__ float fdec(int i)   { return __int_as_float(i >= 0 ? i : (i ^ 0x7FFFFFFF)); }

// FMA-pipe exp, ~2e-6 rel err, no MUFU. Valid for |x| < 80.
__device__ __forceinline__ float fast_exp(float x) {
    x = fmaxf(x, -80.f);
    float t = fmaf(x, 1.4426950408889634f, 12582912.0f);
    int j = __float_as_int(t) - 0x4B400000;
    float f = fmaf(x, 1.4426950408889634f, -(t - 12582912.0f));
    float p = fmaf(1.3333558e-3f, f, 9.6181291e-3f);
    p = fmaf(p, f, 5.5504109e-2f);
    p = fmaf(p, f, 2.4022651e-1f);
    p = fmaf(p, f, 6.9314718e-1f);
    p = fmaf(p, f, 1.0f);
    return __int_as_float(__float_as_int(p) + (j << 23));
}

// ---------------- init (S2) ---------------------------------------------------
__global__ void init_kernel() {
    int t = threadIdx.x;
    if (t < B_) g_max_bits[t] = fenc(-1e30f);
    if (t == 0) g_flag = 0;
}

// ---------------- row norms + nonzero flag ------------------------------------
__global__ void norms_kernel(const float* __restrict__ src, const float* __restrict__ mem) {
    int row = blockIdx.x * 8 + threadIdx.y;
    int lane = threadIdx.x;
    if (row >= B_ + M_) return;
    bool is_src = row < B_;
    const float* base = is_src ? (src + row * D_) : (mem + (row - B_) * D_);
    float s = 0.f;
    #pragma unroll
    for (int d = lane; d < D_; d += 32) { float v = base[d]; s += v * v; }
    #pragma unroll
    for (int o = 16; o; o >>= 1) s += __shfl_xor_sync(0xFFFFFFFFu, s, o);
    if (lane == 0) {
        float nv = fmaxf(sqrtf(s), 1e-8f);
        if (is_src) g_src_norm[row] = nv;
        else {
            g_mem_norm[row - B_] = nv;
            if (s > 0.f) atomicOr(&g_flag, 1);
        }
    }
}

// ---------------- TF32 GEMM, 4-stage cp.async, 256 thr / 8 warps --------------
// warp = 16x32 sub-tile (wm 0..3, wn 0..1). Raw fp32 bits -> hw tf32 truncation.
// MODE 0: (+bias) f32. MODE 2: relu(+bias). MODE 4: cosine max epilogue.
// MODE 5: bf16 store of exp(acc*SCALE) + partial row sums into g_psum.
template <int MODE>
__global__ void __launch_bounds__(256)
tmma64(const float* __restrict__ A, const float* __restrict__ Bm,
       const float* __restrict__ bias, float* __restrict__ C,
       int K, int lda, int ldb, int ldc, int aB, int bB, int cB) {
    __shared__ uint32_t As[STG_][64][20];
    __shared__ uint32_t Bs[STG_][64][20];
    const uint32_t stgB = 64 * 20 * 4;
    int tid = threadIdx.x;
    int rq = tid >> 2;          // 0..63
    int kq = (tid & 3) * 4;     // 0,4,8,12
    const float* Ap = A + (size_t)blockIdx.z * aB + (size_t)(blockIdx.y * 64 + rq) * lda + kq;
    const float* Bp = Bm + (size_t)blockIdx.z * bB + (size_t)(blockIdx.x * 64 + rq) * ldb + kq;
    uint32_t sA = (uint32_t)__cvta_generic_to_shared(&As[0][rq][kq]);
    uint32_t sB = (uint32_t)__cvta_generic_to_shared(&Bs[0][rq][kq]);

    int nIt = K >> 4;
    #pragma unroll
    for (int s = 0; s < STG_ - 1; s++) {
        if (s < nIt) {
            int k0 = s << 4;
            cp16(sA + s * stgB, Ap + k0);
            cp16(sB + s * stgB, Bp + k0);
        }
        asm volatile("cp.async.commit_group;");
    }

    int warp = tid >> 5, lane = tid & 31;
    int wm = warp & 3, wn = warp >> 2;      // 4 m-tiles x 2 n-tiles
    int lr = lane >> 2, lc = lane & 3;

    float acc[4][4];
    #pragma unroll
    for (int nt = 0; nt < 4; nt++)
        #pragma unroll
        for (int q = 0; q < 4; q++) acc[nt][q] = 0.f;

    for (int it = 0; it < nIt; ++it) {
        asm volatile("cp.async.wait_group %0;" :: "n"(STG_ - 2));
        __syncthreads();
        int f = it + STG_ - 1;
        if (f < nIt) {
            int s = f & (STG_ - 1);
            int k0 = f << 4;
            cp16(sA + s * stgB, Ap + k0);
            cp16(sB + s * stgB, Bp + k0);
        }
        asm volatile("cp.async.commit_group;");
        int buf = it & (STG_ - 1);
        #pragma unroll
        for (int k8 = 0; k8 < 16; k8 += 8) {
            uint32_t af[4], bf[4][2];
            int row = wm * 16 + lr;
            af[0] = As[buf][row][k8 + lc];
            af[1] = As[buf][row + 8][k8 + lc];
            af[2] = As[buf][row][k8 + lc + 4];
            af[3] = As[buf][row + 8][k8 + lc + 4];
            #pragma unroll
            for (int nt = 0; nt < 4; nt++) {
                int col = wn * 32 + nt * 8 + lr;
                bf[nt][0] = Bs[buf][col][k8 + lc];
                bf[nt][1] = Bs[buf][col][k8 + lc + 4];
            }
            #pragma unroll
            for (int nt = 0; nt < 4; nt++) mma_tf32(acc[nt], af, bf[nt]);
        }
    }

    if (MODE == 4) {
        int row_base = blockIdx.y * 64, col_base = blockIdx.x * 64;
        float inm[4][2];
        #pragma unroll
        for (int nt = 0; nt < 4; nt++) {
            int col = col_base + wn * 32 + nt * 8 + 2 * lc;
            inm[nt][0] = 1.f / g_mem_norm[col];
            inm[nt][1] = 1.f / g_mem_norm[col + 1];
        }
        #pragma unroll
        for (int hrow = 0; hrow < 2; hrow++) {
            int rl = wm * 16 + lr + hrow * 8;
            float ins = 1.f / g_src_norm[row_base + rl];
            float mx = -1e30f;
            #pragma unroll
            for (int nt = 0; nt < 4; nt++) {
                mx = fmaxf(mx, acc[nt][hrow * 2 + 0] * inm[nt][0]);
                mx = fmaxf(mx, acc[nt][hrow * 2 + 1] * inm[nt][1]);
            }
            mx *= ins;
            mx = fmaxf(mx, __shfl_xor_sync(0xFFFFFFFFu, mx, 1));
            mx = fmaxf(mx, __shfl_xor_sync(0xFFFFFFFFu, mx, 2));
            if (lc == 0) atomicMax(&g_max_bits[row_base + rl], fenc(mx));
        }
        return;
    }

    if (MODE == 5) {
        __nv_bfloat16* Cb16 = (__nv_bfloat16*)C + (size_t)blockIdx.z * cB;
        int pc = blockIdx.x * 2 + wn;
        #pragma unroll
        for (int hrow = 0; hrow < 2; hrow++) {
            float rsum = 0.f;
            int row_g = blockIdx.y * 64 + wm * 16 + lr + hrow * 8;
            #pragma unroll
            for (int nt = 0; nt < 4; nt++) {
                float e0 = fast_exp(acc[nt][hrow * 2 + 0] * SCALE_);
                float e1 = fast_exp(acc[nt][hrow * 2 + 1] * SCALE_);
                rsum += e0 + e1;
                int col_g = blockIdx.x * 64 + wn * 32 + nt * 8 + 2 * lc;
                *(__nv_bfloat162*)&Cb16[(size_t)row_g * ldc + col_g]
                    = __float22bfloat162_rn(make_float2(e0, e1));
            }
            rsum += __shfl_xor_sync(0xFFFFFFFFu, rsum, 1);
            rsum += __shfl_xor_sync(0xFFFFFFFFu, rsum, 2);
            if (lc == 0)
                g_psum[(size_t)pc * (H_ * B_) + blockIdx.z * B_ + row_g] = rsum;
        }
        return;
    }

    #pragma unroll
    for (int nt = 0; nt < 4; nt++) {
        int col_g = blockIdx.x * 64 + wn * 32 + nt * 8 + 2 * lc;
        float bj0 = bias ? bias[col_g] : 0.f;
        float bj1 = bias ? bias[col_g + 1] : 0.f;
        #pragma unroll
        for (int hrow = 0; hrow < 2; hrow++) {
            int row_g = blockIdx.y * 64 + wm * 16 + lr + hrow * 8;
            float v0 = acc[nt][hrow * 2 + 0] + bj0;
            float v1 = acc[nt][hrow * 2 + 1] + bj1;
            if (MODE == 2) { v0 = fmaxf(v0, 0.f); v1 = fmaxf(v1, 0.f); }
            float* Cb = C + (size_t)blockIdx.z * cB;
            *(float2*)&Cb[(size_t)row_g * ldc + col_g] = make_float2(v0, v1);
        }
    }
}

// ---------------- pself/sinv: reduce 64 psum partials + self term -------------
__global__ void pself_kernel(const float* __restrict__ projsrc,
                             float* __restrict__ sinv_o, float* __restrict__ pself_o) {
    int warp = threadIdx.x >> 5, lane = threadIdx.x & 31;
    int ridx = blockIdx.x * 8 + warp;
    int h = ridx >> 8, b = ridx & 255;
    float q = projsrc[b * 768 + h * 32 + lane];
    float k = projsrc[b * 768 + 256 + h * 32 + lane];
    float d = q * k;
    float ps = g_psum[(size_t)lane * (H_ * B_) + ridx]
             + g_psum[(size_t)(lane + 32) * (H_ * B_) + ridx];
    #pragma unroll
    for (int o = 16; o; o >>= 1) {
        d  += __shfl_xor_sync(0xFFFFFFFFu, d, o);
        ps += __shfl_xor_sync(0xFFFFFFFFu, ps, o);
    }
    if (lane == 0) {
        float eself = fast_exp(d * SCALE_);
        float inv = 1.f / (ps + eself);
        sinv_o[ridx]  = inv;
        pself_o[ridx] = eself * inv;
    }
}

// ---------------- AV split-K tf32 over unnormalized bf16 exps -----------------
__global__ void __launch_bounds__(128)
av_tmma(const __nv_bfloat16* __restrict__ probs, const float* __restrict__ kv,
        float* __restrict__ part) {
    __shared__ uint32_t Ps[2][16][132];
    __shared__ uint32_t Vs[2][16][40];
    int tid = threadIdx.x;
    int qb = blockIdx.x, split = blockIdx.y, h = blockIdx.z;

    const __nv_bfloat16* Prow = probs + ((size_t)(h * B_ + qb * 128 + tid)) * M_ + split * KSPLIT_;
    int vr = tid >> 3, vc = (tid & 7) * 4;
    const float* Vbase = kv + 256 + h * 32 + vc;

    float pv[16]; float4 vv;
    {
        uint4 u0 = *(const uint4*)(Prow);
        uint4 u1 = *(const uint4*)(Prow + 8);
        float2 f;
        f = __bfloat1622float2(*(__nv_bfloat162*)&u0.x); pv[0]=f.x; pv[1]=f.y;
        f = __bfloat1622float2(*(__nv_bfloat162*)&u0.y); pv[2]=f.x; pv[3]=f.y;
        f = __bfloat1622float2(*(__nv_bfloat162*)&u0.z); pv[4]=f.x; pv[5]=f.y;
        f = __bfloat1622float2(*(__nv_bfloat162*)&u0.w); pv[6]=f.x; pv[7]=f.y;
        f = __bfloat1622float2(*(__nv_bfloat162*)&u1.x); pv[8]=f.x; pv[9]=f.y;
        f = __bfloat1622float2(*(__nv_bfloat162*)&u1.y); pv[10]=f.x; pv[11]=f.y;
        f = __bfloat1622float2(*(__nv_bfloat162*)&u1.z); pv[12]=f.x; pv[13]=f.y;
        f = __bfloat1622float2(*(__nv_bfloat162*)&u1.w); pv[14]=f.x; pv[15]=f.y;
    }
    vv = *(const float4*)(Vbase + (size_t)(split * KSPLIT_ + vr) * 512);
    #pragma unroll
    for (int q = 0; q < 16; q++) Ps[0][q][tid] = f2tf32(pv[q]);
    Vs[0][vr][vc + 0] = f2tf32(vv.x); Vs[0][vr][vc + 1] = f2tf32(vv.y);
    Vs[0][vr][vc + 2] = f2tf32(vv.z); Vs[0][vr][vc + 3] = f2tf32(vv.w);
    __syncthreads();

    int warp = tid >> 5, lane = tid & 31;
    int lr = lane >> 2, lc = lane & 3;

    float acc[2][4][4];
    #pragma unroll
    for (int mt = 0; mt < 2; mt++)
        #pragma unroll
        for (int nt = 0; nt < 4; nt++)
            #pragma unroll
            for (int q = 0; q < 4; q++) acc[mt][nt][q] = 0.f;

    const int nIt = KSPLIT_ / 16;   // 8
    for (int it = 0; it < nIt; ++it) {
        int buf = it & 1;
        bool more = (it + 1) < nIt;
        if (more) {
            int k0 = (it + 1) * 16;
            uint4 u0 = *(const uint4*)(Prow + k0);
            uint4 u1 = *(const uint4*)(Prow + k0 + 8);
            float2 f;
            f = __bfloat1622float2(*(__nv_bfloat162*)&u0.x); pv[0]=f.x; pv[1]=f.y;
            f = __bfloat1622float2(*(__nv_bfloat162*)&u0.y); pv[2]=f.x; pv[3]=f.y;
            f = __bfloat1622float2(*(__nv_bfloat162*)&u0.z); pv[4]=f.x; pv[5]=f.y;
            f = __bfloat1622float2(*(__nv_bfloat162*)&u0.w); pv[6]=f.x; pv[7]=f.y;
            f = __bfloat1622float2(*(__nv_bfloat162*)&u1.x); pv[8]=f.x; pv[9]=f.y;
            f = __bfloat1622float2(*(__nv_bfloat162*)&u1.y); pv[10]=f.x; pv[11]=f.y;
            f = __bfloat1622float2(*(__nv_bfloat162*)&u1.z); pv[12]=f.x; pv[13]=f.y;
            f = __bfloat1622float2(*(__nv_bfloat162*)&u1.w); pv[14]=f.x; pv[15]=f.y;
            vv = *(const float4*)(Vbase + (size_t)(split * KSPLIT_ + k0 + vr) * 512);
        }
        #pragma unroll
        for (int k8 = 0; k8 < 16; k8 += 8) {
            uint32_t af[2][4], bf[4][2];
            #pragma unroll
            for (int mt = 0; mt < 2; mt++) {
                int row = warp * 32 + mt * 16 + lr;
                af[mt][0] = Ps[buf][k8 + lc][row];
                af[mt][1] = Ps[buf][k8 + lc][row + 8];
                af[mt][2] = Ps[buf][k8 + lc + 4][row];
                af[mt][3] = Ps[buf][k8 + lc + 4][row + 8];
            }
            #pragma unroll
            for (int nt = 0; nt < 4; nt++) {
                int col = nt * 8 + lr;
                bf[nt][0] = Vs[buf][k8 + lc][col];
                bf[nt][1] = Vs[buf][k8 + lc + 4][col];
            }
            #pragma unroll
            for (int mt = 0; mt < 2; mt++)
                #pragma unroll
                for (int nt = 0; nt < 4; nt++) mma_tf32(acc[mt][nt], af[mt], bf[nt]);
        }
        if (more) {
            int nb = buf ^ 1;
            #pragma unroll
            for (int q = 0; q < 16; q++) Ps[nb][q][tid] = f2tf32(pv[q]);
            Vs[nb][vr][vc + 0] = f2tf32(vv.x); Vs[nb][vr][vc + 1] = f2tf32(vv.y);
            Vs[nb][vr][vc + 2] = f2tf32(vv.z); Vs[nb][vr][vc + 3] = f2tf32(vv.w);
            __syncthreads();
        }
    }

    float* Pb = part + (size_t)split * (B_ * D_);
    #pragma unroll
    for (int mt = 0; mt < 2; mt++) {
        #pragma unroll
        for (int nt = 0; nt < 4; nt++) {
            int col = nt * 8 + 2 * lc;
            #pragma unroll
            for (int hrow = 0; hrow < 2; hrow++) {
                int row_g = qb * 128 + warp * 32 + mt * 16 + lr + hrow * 8;
                *(float2*)&Pb[(size_t)row_g * D_ + h * 32 + col]
                    = make_float2(acc[mt][nt][hrow * 2 + 0], acc[mt][nt][hrow * 2 + 1]);
            }
        }
    }
}

// ---------------- reduce AV partials, normalize, add self term -> ctx ---------
__global__ void reduce_ctx_kernel(const float* __restrict__ part, const float* __restrict__ pself,
                                  const float* __restrict__ sinv, const float* __restrict__ projsrc,
                                  float* __restrict__ ctx) {
    int b = blockIdx.x, d = threadIdx.x;
    int h = d >> 5;
    float s = 0.f;
    #pragma unroll
    for (int sp = 0; sp < NSPLIT_; sp++) s += part[(size_t)sp * (B_ * D_) + b * D_ + d];
    int ridx = h * B_ + b;
    s = s * sinv[ridx] + pself[ridx] * projsrc[b * 768 + 512 + d];
    ctx[b * D_ + d] = s;
}

// ---------------- LN with fused split-K reduce -------------------------------
__global__ void ln_split_kernel(const float* __restrict__ a, const float* __restrict__ part,
                                int nsplit, const float* __restrict__ bias,
                                const float* __restrict__ g, const float* __restrict__ be,
                                float* __restrict__ out) {
    int w = threadIdx.x >> 5, lane = threadIdx.x & 31;
    int row = blockIdx.x * 8 + w;
    size_t base = (size_t)row * D_ + lane * 8;
    float4 a0 = *(const float4*)(a + base);
    float4 a1 = *(const float4*)(a + base + 4);
    float x[8] = {a0.x, a0.y, a0.z, a0.w, a1.x, a1.y, a1.z, a1.w};
    for (int z = 0; z < nsplit; z++) {
        const float* pp = part + (size_t)z * (B_ * D_) + base;
        float4 p0 = *(const float4*)pp;
        float4 p1 = *(const float4*)(pp + 4);
        x[0]+=p0.x; x[1]+=p0.y; x[2]+=p0.z; x[3]+=p0.w;
        x[4]+=p1.x; x[5]+=p1.y; x[6]+=p1.z; x[7]+=p1.w;
    }
    float4 bb0 = *(const float4*)(bias + lane * 8);
    float4 bb1 = *(const float4*)(bias + lane * 8 + 4);
    x[0]+=bb0.x; x[1]+=bb0.y; x[2]+=bb0.z; x[3]+=bb0.w;
    x[4]+=bb1.x; x[5]+=bb1.y; x[6]+=bb1.z; x[7]+=bb1.w;

    float s = 0.f;
    #pragma unroll
    for (int j = 0; j < 8; j++) s += x[j];
    #pragma unroll
    for (int o = 16; o; o >>= 1) s += __shfl_xor_sync(0xFFFFFFFFu, s, o);
    float mean = s * (1.f / D_);
    float v = 0.f;
    #pragma unroll
    for (int j = 0; j < 8; j++) { float c = x[j] - mean; v += c * c; }
    #pragma unroll
    for (int o = 16; o; o >>= 1) v += __shfl_xor_sync(0xFFFFFFFFu, v, o);
    float rstd = rsqrtf(v * (1.f / D_) + 1e-5f);
    float4 g0 = *(const float4*)(g + lane * 8);
    float4 g1 = *(const float4*)(g + lane * 8 + 4);
    float4 e0 = *(const float4*)(be + lane * 8);
    float4 e1 = *(const float4*)(be + lane * 8 + 4);
    float gg[8] = {g0.x, g0.y, g0.z, g0.w, g1.x, g1.y, g1.z, g1.w};
    float ee[8] = {e0.x, e0.y, e0.z, e0.w, e1.x, e1.y, e1.z, e1.w};
    float o8[8];
    #pragma unroll
    for (int j = 0; j < 8; j++) o8[j] = (x[j] - mean) * rstd * gg[j] + ee[j];
    *(float4*)(out + base)     = make_float4(o8[0], o8[1], o8[2], o8[3]);
    *(float4*)(out + base + 4) = make_float4(o8[4], o8[5], o8[6], o8[7]);
}

// ---------------- scatter prep: ballot-scan prefix ----------------------------
__global__ void scatter_prep_kernel(const int* __restrict__ ptrp) {
    __shared__ int wcnt[8];
    int t = threadIdx.x, w = t >> 5, lane = t & 31;
    int flag = g_flag;
    float s = flag ? (1.0f - fdec(g_max_bits[t])) : 1.0f;
    int ptr = *ptrp;
    long long forced = (long long)M_ - (long long)ptr;
    int cond = (s > THR_) || ((long long)t < forced);
    unsigned mask = __ballot_sync(0xFFFFFFFFu, cond);
    int lpref = __popc(mask & ((1u << lane) - 1u));
    if (lane == 31) wcnt[w] = lpref + cond;
    #pragma unroll
    for (int j = 0; j < 8; j++) g_row_src[t + j * 256] = -1;
    __syncthreads();
    int wbase = 0;
    #pragma unroll
    for (int i = 0; i < 8; i++) { if (i < w) wbase += wcnt[i]; }
    g_upd_s[t] = s;
    if (cond) {
        long long p = (long long)ptr + (wbase + lpref);
        int idx = (int)(p % M_); if (idx < 0) idx += M_;
        g_row_src[idx] = t;
    }
}

// ---------------- full-coverage memory update --------------------------------
__global__ void update_kernel(const float* __restrict__ mem, const float* __restrict__ mom,
                              const float* __restrict__ scores,
                              float* __restrict__ out_mem, float* __restrict__ out_mom,
                              float* __restrict__ out_sc) {
    int row = blockIdx.x, t = threadIdx.x;
    int i = g_row_src[row];
    size_t o = (size_t)row * D_ + t;
    float mval = mem[o], mo = mom[o];
    if (i >= 0) {
        float diff = g_h[i * D_ + t] - mval;
        float nm = MOM_ * mo + (1.0f - MOM_) * diff;
        out_mem[o] = mval + LR_ * nm;
        out_mom[o] = nm;
    } else {
        out_mem[o] = mval;
        out_mom[o] = mo;
    }
    if (t == 0) out_sc[row] = (i >= 0) ? g_upd_s[i] : scores[row];
}

// ---------------- launch -----------------------------------------------------
extern "C" void kernel_launch(void* const* d_in, const int* in_sizes, int n_in,
                              void* d_out, int out_size) {
    const float* src       = (const float*)d_in[0];
    const float* memory    = (const float*)d_in[1];
    const float* momentum  = (const float*)d_in[2];
    const float* scores    = (const float*)d_in[3];
    const float* in_proj_w = (const float*)d_in[4];
    const float* in_proj_b = (const float*)d_in[5];
    const float* out_w     = (const float*)d_in[6];
    const float* out_b     = (const float*)d_in[7];
    const float* w1        = (const float*)d_in[8];
    const float* b1        = (const float*)d_in[9];
    const float* w2        = (const float*)d_in[10];
    const float* b2        = (const float*)d_in[11];
    const float* g1        = (const float*)d_in[12];
    const float* be1       = (const float*)d_in[13];
    const float* g2        = (const float*)d_in[14];
    const float* be2       = (const float*)d_in[15];
    const int*   ptr       = (const int*)d_in[16];

    float* out     = (float*)d_out;
    float* out_mem = out + B_ * D_;
    float* out_mom = out_mem + M_ * D_;
    float* out_sc  = out_mom + M_ * D_;

    float *proj_p, *kv_p, *pself_p, *sinv_p, *part_p, *ap_p, *fp_p, *ctx_p, *h_p, *hid_p;
    __nv_bfloat16* log_p;
    cudaGetSymbolAddress((void**)&proj_p,  g_proj_src);
    cudaGetSymbolAddress((void**)&kv_p,    g_kv_mem);
    cudaGetSymbolAddress((void**)&log_p,   g_logits);
    cudaGetSymbolAddress((void**)&pself_p, g_pself);
    cudaGetSymbolAddress((void**)&sinv_p,  g_sinv);
    cudaGetSymbolAddress((void**)&part_p,  g_ctx_part);
    cudaGetSymbolAddress((void**)&ap_p,    g_attn_part);
    cudaGetSymbolAddress((void**)&fp_p,    g_ff_part);
    cudaGetSymbolAddress((void**)&ctx_p,   g_ctx);
    cudaGetSymbolAddress((void**)&h_p,     g_h);
    cudaGetSymbolAddress((void**)&hid_p,   g_hidden);

    static cudaStream_t s1 = nullptr, s2 = nullptr;
    static cudaEvent_t eFork = nullptr, eKV = nullptr, eS2 = nullptr,
                       eLN1 = nullptr, eUpd = nullptr, eLog = nullptr, ePS = nullptr;
    if (!s1) {
        cudaStreamCreateWithFlags(&s1, cudaStreamNonBlocking);
        cudaStreamCreateWithFlags(&s2, cudaStreamNonBlocking);
        cudaEventCreateWithFlags(&eFork, cudaEventDisableTiming);
        cudaEventCreateWithFlags(&eKV,   cudaEventDisableTiming);
        cudaEventCreateWithFlags(&eS2,   cudaEventDisableTiming);
        cudaEventCreateWithFlags(&eLN1,  cudaEventDisableTiming);
        cudaEventCreateWithFlags(&eUpd,  cudaEventDisableTiming);
        cudaEventCreateWithFlags(&eLog,  cudaEventDisableTiming);
        cudaEventCreateWithFlags(&ePS,   cudaEventDisableTiming);
    }

    // ---- fork ----
    cudaEventRecord(eFork, 0);
    cudaStreamWaitEvent(s1, eFork, 0);
    cudaStreamWaitEvent(s2, eFork, 0);

    // S1: memory k|v projection [2048,512] (tf32)
    tmma64<0><<<dim3(8, 32, 1), 256, 0, s1>>>(memory, in_proj_w + D_ * D_, in_proj_b + D_, kv_p,
                                              256, 256, 256, 512, 0, 0, 0);
    cudaEventRecord(eKV, s1);

    // S2: init -> norms (+flag) -> cosine (tf32, MODE 4) -> scatter prep
    init_kernel<<<1, 256, 0, s2>>>();
    norms_kernel<<<(B_ + M_ + 7) / 8, dim3(32, 8), 0, s2>>>(src, memory);
    tmma64<4><<<dim3(32, 4, 1), 256, 0, s2>>>(src, memory, nullptr, nullptr,
                                              256, 256, 256, 0, 0, 0, 0);
    scatter_prep_kernel<<<1, 256, 0, s2>>>(ptr);
    cudaEventRecord(eS2, s2);

    // S0: src projections [256,768] (tf32)
    tmma64<0><<<dim3(12, 4, 1), 256>>>(src, in_proj_w, in_proj_b, proj_p,
                                       256, 256, 256, 768, 0, 0, 0);

    // S0: logits GEMM with exp epilogue (bf16 unnormalized exps + psum)
    cudaStreamWaitEvent(0, eKV, 0);
    tmma64<5><<<dim3(32, 4, H_), 256>>>(proj_p, kv_p, nullptr, (float*)log_p,
                                        32, 768, 512, 2048, 32, 32, B_ * M_);
    cudaEventRecord(eLog, 0);

    // S2 (concurrent with AV): pself/sinv reduction
    cudaStreamWaitEvent(s2, eLog, 0);
    pself_kernel<<<B_ * H_ / 8, 256, 0, s2>>>(proj_p, sinv_p, pself_p);
    cudaEventRecord(ePS, s2);

    // S0: AV directly on unnormalized exps
    av_tmma<<<dim3(2, NSPLIT_, H_), 128>>>(log_p, kv_p, part_p);
    cudaStreamWaitEvent(0, ePS, 0);
    reduce_ctx_kernel<<<B_, 256>>>(part_p, pself_p, sinv_p, proj_p, ctx_p);

    // out-proj split-K x4 (tf32) -> partials; LN1 fuses reduce + bias
    tmma64<0><<<dim3(4, 4, 4), 256>>>(ctx_p, out_w, nullptr, ap_p,
                                      64, 256, 256, 256, 64, 64, B_ * D_);
    ln_split_kernel<<<B_ / 8, 256>>>(src, ap_p, 4, out_b, g1, be1, h_p);
    cudaEventRecord(eLN1, 0);

    // S1: memory update path (needs h + scatter map), overlaps FFN
    cudaStreamWaitEvent(s1, eLN1, 0);
    cudaStreamWaitEvent(s1, eS2, 0);
    update_kernel<<<M_, 256, 0, s1>>>(memory, momentum, scores, out_mem, out_mom, out_sc);
    cudaEventRecord(eUpd, s1);

    // S0: FFN1 (tf32 relu+bias), FFN2 split-K x16 (tf32); LN2 fuses reduce
    tmma64<2><<<dim3(16, 4, 1), 256>>>(h_p, w1, b1, hid_p,
                                       256, 256, 256, 1024, 0, 0, 0);
    tmma64<0><<<dim3(4, 4, FSPLIT_), 256>>>(hid_p, w2, nullptr, fp_p,
                                            1024 / FSPLIT_, 1024, 1024, 256,
                                            1024 / FSPLIT_, 1024 / FSPLIT_, B_ * D_);
    ln_split_kernel<<<B_ / 8, 256>>>(h_p, fp_p, FSPLIT_, b2, g2, be2, out);

    // ---- join ----
    cudaStreamWaitEvent(0, eUpd, 0);
}

// round 15
// speedup vs baseline: 1.0774x; 1.0774x over previous
#include <cuda_runtime.h>
#include <cuda_bf16.h>
#include <math.h>
#include <stdint.h>

#define B_   256
#define D_   256
#define H_   8
#define HD_  32
#define FF_  1024
#define M_   2048
#define SCALE_ 0.17677669529663687f   /* 1/sqrt(32) */
#define THR_ 0.5f
#define MOM_ 0.9f
#define LR_  0.1f
#define NSPLIT_ 16
#define KSPLIT_ (M_ / NSPLIT_)   /* 128 keys per split */
#define FSPLIT_ 16               /* FFN2 split-K */
#define NPC_ 64                  /* psum partial columns */
#define STG_ 4                   /* cp.async pipeline stages */

// ---------------- scratch (device globals) -----------------------------------
__device__ float g_proj_src[B_ * 3 * D_];
__device__ float g_kv_mem[M_ * 2 * D_];
__device__ __nv_bfloat16 g_logits[H_ * B_ * M_];   // UNNORMALIZED exp(logit*scale), bf16
__device__ float g_psum[NPC_ * H_ * B_];
__device__ float g_pself[H_ * B_];
__device__ float g_sinv[H_ * B_];
__device__ float g_ctx_part[NSPLIT_ * B_ * D_];
__device__ float g_attn_part[4 * B_ * D_];
__device__ float g_ff_part[FSPLIT_ * B_ * D_];
__device__ float g_src_norm[B_];
__device__ float g_mem_norm[M_];
__device__ int   g_max_bits[B_];
__device__ float g_ctx[B_ * D_];
__device__ float g_h[B_ * D_];
__device__ float g_hidden[B_ * FF_];
__device__ int   g_row_src[M_];
__device__ float g_upd_s[B_];

__device__ __forceinline__ uint32_t f2tf32(float f) {
    uint32_t r;
    asm("cvt.rna.tf32.f32 %0, %1;" : "=r"(r) : "f"(f));
    return r;
}
__device__ __forceinline__ void mma_tf32(float c[4], const uint32_t a[4], const uint32_t b[2]) {
    asm volatile(
        "mma.sync.aligned.m16n8k8.row.col.f32.tf32.tf32.f32 "
        "{%0,%1,%2,%3}, {%4,%5,%6,%7}, {%8,%9}, {%0,%1,%2,%3};"
        : "+f"(c[0]), "+f"(c[1]), "+f"(c[2]), "+f"(c[3])
        : "r"(a[0]), "r"(a[1]), "r"(a[2]), "r"(a[3]), "r"(b[0]), "r"(b[1]));
}
__device__ __forceinline__ void cp16(uint32_t saddr, const float* g) {
    asm volatile("cp.async.cg.shared.global [%0], [%1], 16;" :: "r"(saddr), "l"(g));
}
__device__ __forceinline__ int   fenc(float f) { int i = __float_as_int(f); return i >= 0 ? i : (i ^ 0x7FFFFFFF); }
__device__ __forceinline__ float fdec(int i)   { return __int_as_float(i >= 0 ? i : (i ^ 0x7FFFFFFF)); }

// FMA-pipe exp, ~2e-6 rel err, no MUFU. Valid for |x| < 80.
__device__ __forceinline__ float fast_exp(float x) {
    x = fmaxf(x, -80.f);
    float t = fmaf(x, 1.4426950408889634f, 12582912.0f);
    int j = __float_as_int(t) - 0x4B400000;
    float f = fmaf(x, 1.4426950408889634f, -(t - 12582912.0f));
    float p = fmaf(1.3333558e-3f, f, 9.6181291e-3f);
    p = fmaf(p, f, 5.5504109e-2f);
    p = fmaf(p, f, 2.4022651e-1f);
    p = fmaf(p, f, 6.9314718e-1f);
    p = fmaf(p, f, 1.0f);
    return __int_as_float(__float_as_int(p) + (j << 23));
}

// ---------------- row norms (+g_max_bits init in block 0) ---------------------
__global__ void norms_kernel(const float* __restrict__ src, const float* __restrict__ mem) {
    if (blockIdx.x == 0) {
        int t = threadIdx.y * 32 + threadIdx.x;
        g_max_bits[t] = fenc(-1e30f);
    }
    int row = blockIdx.x * 8 + threadIdx.y;
    int lane = threadIdx.x;
    if (row >= B_ + M_) return;
    bool is_src = row < B_;
    const float* base = is_src ? (src + row * D_) : (mem + (row - B_) * D_);
    float s = 0.f;
    #pragma unroll
    for (int d = lane; d < D_; d += 32) { float v = base[d]; s += v * v; }
    #pragma unroll
    for (int o = 16; o; o >>= 1) s += __shfl_xor_sync(0xFFFFFFFFu, s, o);
    if (lane == 0) {
        float nv = fmaxf(sqrtf(s), 1e-8f);
        if (is_src) g_src_norm[row] = nv;
        else        g_mem_norm[row - B_] = nv;
    }
}

// ---------------- TF32 GEMM, 4-stage cp.async, 128 thr ------------------------
// smem [row][k] stride 20; raw fp32 bits -> hw tf32 truncation.
// MODE 0: (+bias) f32. MODE 2: relu(+bias). MODE 4: cosine max epilogue.
// MODE 5: bf16 store of exp(acc*SCALE) + partial row sums into g_psum.
template <int MODE>
__global__ void __launch_bounds__(128)
tmma64(const float* __restrict__ A, const float* __restrict__ Bm,
       const float* __restrict__ bias, float* __restrict__ C,
       int K, int lda, int ldb, int ldc, int aB, int bB, int cB) {
    __shared__ uint32_t As[STG_][64][20];
    __shared__ uint32_t Bs[STG_][64][20];
    const uint32_t stgB = 64 * 20 * 4;
    int tid = threadIdx.x;
    int rq = tid >> 2;
    int kq = (tid & 3) * 4;
    const float* Ap  = A + (size_t)blockIdx.z * aB + (size_t)(blockIdx.y * 64 + rq) * lda + kq;
    const float* Bp  = Bm + (size_t)blockIdx.z * bB + (size_t)(blockIdx.x * 64 + rq) * ldb + kq;
    const float* Ap2 = Ap + 32 * lda;
    const float* Bp2 = Bp + 32 * ldb;
    uint32_t sA0 = (uint32_t)__cvta_generic_to_shared(&As[0][rq][kq]);
    uint32_t sA1 = (uint32_t)__cvta_generic_to_shared(&As[0][rq + 32][kq]);
    uint32_t sB0 = (uint32_t)__cvta_generic_to_shared(&Bs[0][rq][kq]);
    uint32_t sB1 = (uint32_t)__cvta_generic_to_shared(&Bs[0][rq + 32][kq]);

    int nIt = K >> 4;
    #pragma unroll
    for (int s = 0; s < STG_ - 1; s++) {
        if (s < nIt) {
            int k0 = s << 4;
            cp16(sA0 + s * stgB, Ap + k0);
            cp16(sA1 + s * stgB, Ap2 + k0);
            cp16(sB0 + s * stgB, Bp + k0);
            cp16(sB1 + s * stgB, Bp2 + k0);
        }
        asm volatile("cp.async.commit_group;");
    }

    int warp = tid >> 5, lane = tid & 31;
    int wm = warp & 1, wn = warp >> 1;
    int lr = lane >> 2, lc = lane & 3;

    float acc[2][4][4];
    #pragma unroll
    for (int mt = 0; mt < 2; mt++)
        #pragma unroll
        for (int nt = 0; nt < 4; nt++)
            #pragma unroll
            for (int q = 0; q < 4; q++) acc[mt][nt][q] = 0.f;

    for (int it = 0; it < nIt; ++it) {
        asm volatile("cp.async.wait_group %0;" :: "n"(STG_ - 2));
        __syncthreads();
        int f = it + STG_ - 1;
        if (f < nIt) {
            int s = f & (STG_ - 1);
            int k0 = f << 4;
            cp16(sA0 + s * stgB, Ap + k0);
            cp16(sA1 + s * stgB, Ap2 + k0);
            cp16(sB0 + s * stgB, Bp + k0);
            cp16(sB1 + s * stgB, Bp2 + k0);
        }
        asm volatile("cp.async.commit_group;");
        int buf = it & (STG_ - 1);
        #pragma unroll
        for (int k8 = 0; k8 < 16; k8 += 8) {
            uint32_t af[2][4], bf[4][2];
            #pragma unroll
            for (int mt = 0; mt < 2; mt++) {
                int row = wm * 32 + mt * 16 + lr;
                af[mt][0] = As[buf][row][k8 + lc];
                af[mt][1] = As[buf][row + 8][k8 + lc];
                af[mt][2] = As[buf][row][k8 + lc + 4];
                af[mt][3] = As[buf][row + 8][k8 + lc + 4];
            }
            #pragma unroll
            for (int nt = 0; nt < 4; nt++) {
                int col = wn * 32 + nt * 8 + lr;
                bf[nt][0] = Bs[buf][col][k8 + lc];
                bf[nt][1] = Bs[buf][col][k8 + lc + 4];
            }
            #pragma unroll
            for (int mt = 0; mt < 2; mt++)
                #pragma unroll
                for (int nt = 0; nt < 4; nt++) mma_tf32(acc[mt][nt], af[mt], bf[nt]);
        }
    }

    if (MODE == 4) {
        int row_base = blockIdx.y * 64, col_base = blockIdx.x * 64;
        float inm[4][2];
        #pragma unroll
        for (int nt = 0; nt < 4; nt++) {
            int col = col_base + wn * 32 + nt * 8 + 2 * lc;
            inm[nt][0] = 1.f / g_mem_norm[col];
            inm[nt][1] = 1.f / g_mem_norm[col + 1];
        }
        #pragma unroll
        for (int mt = 0; mt < 2; mt++) {
            #pragma unroll
            for (int hrow = 0; hrow < 2; hrow++) {
                int rl = wm * 32 + mt * 16 + lr + hrow * 8;
                float ins = 1.f / g_src_norm[row_base + rl];
                float mx = -1e30f;
                #pragma unroll
                for (int nt = 0; nt < 4; nt++) {
                    mx = fmaxf(mx, acc[mt][nt][hrow * 2 + 0] * inm[nt][0]);
                    mx = fmaxf(mx, acc[mt][nt][hrow * 2 + 1] * inm[nt][1]);
                }
                mx *= ins;
                mx = fmaxf(mx, __shfl_xor_sync(0xFFFFFFFFu, mx, 1));
                mx = fmaxf(mx, __shfl_xor_sync(0xFFFFFFFFu, mx, 2));
                if (lc == 0) atomicMax(&g_max_bits[row_base + rl], fenc(mx));
            }
        }
        return;
    }

    if (MODE == 5) {
        __nv_bfloat16* Cb16 = (__nv_bfloat16*)C + (size_t)blockIdx.z * cB;
        int pc = blockIdx.x * 2 + wn;
        #pragma unroll
        for (int mt = 0; mt < 2; mt++) {
            #pragma unroll
            for (int hrow = 0; hrow < 2; hrow++) {
                float rsum = 0.f;
                #pragma unroll
                for (int nt = 0; nt < 4; nt++) {
                    float e0 = fast_exp(acc[mt][nt][hrow * 2 + 0] * SCALE_);
                    float e1 = fast_exp(acc[mt][nt][hrow * 2 + 1] * SCALE_);
                    rsum += e0 + e1;
                    int col_g = blockIdx.x * 64 + wn * 32 + nt * 8 + 2 * lc;
                    int row_g = blockIdx.y * 64 + wm * 32 + mt * 16 + lr + hrow * 8;
                    *(__nv_bfloat162*)&Cb16[(size_t)row_g * ldc + col_g]
                        = __float22bfloat162_rn(make_float2(e0, e1));
                }
                rsum += __shfl_xor_sync(0xFFFFFFFFu, rsum, 1);
                rsum += __shfl_xor_sync(0xFFFFFFFFu, rsum, 2);
                if (lc == 0) {
                    int row_g = blockIdx.y * 64 + wm * 32 + mt * 16 + lr + hrow * 8;
                    g_psum[(size_t)pc * (H_ * B_) + blockIdx.z * B_ + row_g] = rsum;
                }
            }
        }
        return;
    }

    #pragma unroll
    for (int mt = 0; mt < 2; mt++) {
        #pragma unroll
        for (int nt = 0; nt < 4; nt++) {
            int col_g = blockIdx.x * 64 + wn * 32 + nt * 8 + 2 * lc;
            float bj0 = bias ? bias[col_g] : 0.f;
            float bj1 = bias ? bias[col_g + 1] : 0.f;
            #pragma unroll
            for (int hrow = 0; hrow < 2; hrow++) {
                int row_g = blockIdx.y * 64 + wm * 32 + mt * 16 + lr + hrow * 8;
                float v0 = acc[mt][nt][hrow * 2 + 0] + bj0;
                float v1 = acc[mt][nt][hrow * 2 + 1] + bj1;
                if (MODE == 2) { v0 = fmaxf(v0, 0.f); v1 = fmaxf(v1, 0.f); }
                float* Cb = C + (size_t)blockIdx.z * cB;
                *(float2*)&Cb[(size_t)row_g * ldc + col_g] = make_float2(v0, v1);
            }
        }
    }
}

// ---------------- pself/sinv: reduce 64 psum partials + self term -------------
__global__ void pself_kernel(const float* __restrict__ projsrc,
                             float* __restrict__ sinv_o, float* __restrict__ pself_o) {
    int warp = threadIdx.x >> 5, lane = threadIdx.x & 31;
    int ridx = blockIdx.x * 8 + warp;
    int h = ridx >> 8, b = ridx & 255;
    float q = projsrc[b * 768 + h * 32 + lane];
    float k = projsrc[b * 768 + 256 + h * 32 + lane];
    float d = q * k;
    float ps = g_psum[(size_t)lane * (H_ * B_) + ridx]
             + g_psum[(size_t)(lane + 32) * (H_ * B_) + ridx];
    #pragma unroll
    for (int o = 16; o; o >>= 1) {
        d  += __shfl_xor_sync(0xFFFFFFFFu, d, o);
        ps += __shfl_xor_sync(0xFFFFFFFFu, ps, o);
    }
    if (lane == 0) {
        float eself = fast_exp(d * SCALE_);
        float inv = 1.f / (ps + eself);
        sinv_o[ridx]  = inv;
        pself_o[ridx] = eself * inv;
    }
}

// ---------------- AV split-K tf32 over unnormalized bf16 exps -----------------
__global__ void __launch_bounds__(128)
av_tmma(const __nv_bfloat16* __restrict__ probs, const float* __restrict__ kv,
        float* __restrict__ part) {
    __shared__ uint32_t Ps[2][16][132];
    __shared__ uint32_t Vs[2][16][40];
    int tid = threadIdx.x;
    int qb = blockIdx.x, split = blockIdx.y, h = blockIdx.z;

    const __nv_bfloat16* Prow = probs + ((size_t)(h * B_ + qb * 128 + tid)) * M_ + split * KSPLIT_;
    int vr = tid >> 3, vc = (tid & 7) * 4;
    const float* Vbase = kv + 256 + h * 32 + vc;

    float pv[16]; float4 vv;
    {
        uint4 u0 = *(const uint4*)(Prow);
        uint4 u1 = *(const uint4*)(Prow + 8);
        float2 f;
        f = __bfloat1622float2(*(__nv_bfloat162*)&u0.x); pv[0]=f.x; pv[1]=f.y;
        f = __bfloat1622float2(*(__nv_bfloat162*)&u0.y); pv[2]=f.x; pv[3]=f.y;
        f = __bfloat1622float2(*(__nv_bfloat162*)&u0.z); pv[4]=f.x; pv[5]=f.y;
        f = __bfloat1622float2(*(__nv_bfloat162*)&u0.w); pv[6]=f.x; pv[7]=f.y;
        f = __bfloat1622float2(*(__nv_bfloat162*)&u1.x); pv[8]=f.x; pv[9]=f.y;
        f = __bfloat1622float2(*(__nv_bfloat162*)&u1.y); pv[10]=f.x; pv[11]=f.y;
        f = __bfloat1622float2(*(__nv_bfloat162*)&u1.z); pv[12]=f.x; pv[13]=f.y;
        f = __bfloat1622float2(*(__nv_bfloat162*)&u1.w); pv[14]=f.x; pv[15]=f.y;
    }
    vv = *(const float4*)(Vbase + (size_t)(split * KSPLIT_ + vr) * 512);
    #pragma unroll
    for (int q = 0; q < 16; q++) Ps[0][q][tid] = f2tf32(pv[q]);
    Vs[0][vr][vc + 0] = f2tf32(vv.x); Vs[0][vr][vc + 1] = f2tf32(vv.y);
    Vs[0][vr][vc + 2] = f2tf32(vv.z); Vs[0][vr][vc + 3] = f2tf32(vv.w);
    __syncthreads();

    int warp = tid >> 5, lane = tid & 31;
    int lr = lane >> 2, lc = lane & 3;

    float acc[2][4][4];
    #pragma unroll
    for (int mt = 0; mt < 2; mt++)
        #pragma unroll
        for (int nt = 0; nt < 4; nt++)
            #pragma unroll
            for (int q = 0; q < 4; q++) acc[mt][nt][q] = 0.f;

    const int nIt = KSPLIT_ / 16;   // 8
    for (int it = 0; it < nIt; ++it) {
        int buf = it & 1;
        bool more = (it + 1) < nIt;
        if (more) {
            int k0 = (it + 1) * 16;
            uint4 u0 = *(const uint4*)(Prow + k0);
            uint4 u1 = *(const uint4*)(Prow + k0 + 8);
            float2 f;
            f = __bfloat1622float2(*(__nv_bfloat162*)&u0.x); pv[0]=f.x; pv[1]=f.y;
            f = __bfloat1622float2(*(__nv_bfloat162*)&u0.y); pv[2]=f.x; pv[3]=f.y;
            f = __bfloat1622float2(*(__nv_bfloat162*)&u0.z); pv[4]=f.x; pv[5]=f.y;
            f = __bfloat1622float2(*(__nv_bfloat162*)&u0.w); pv[6]=f.x; pv[7]=f.y;
            f = __bfloat1622float2(*(__nv_bfloat162*)&u1.x); pv[8]=f.x; pv[9]=f.y;
            f = __bfloat1622float2(*(__nv_bfloat162*)&u1.y); pv[10]=f.x; pv[11]=f.y;
            f = __bfloat1622float2(*(__nv_bfloat162*)&u1.z); pv[12]=f.x; pv[13]=f.y;
            f = __bfloat1622float2(*(__nv_bfloat162*)&u1.w); pv[14]=f.x; pv[15]=f.y;
            vv = *(const float4*)(Vbase + (size_t)(split * KSPLIT_ + k0 + vr) * 512);
        }
        #pragma unroll
        for (int k8 = 0; k8 < 16; k8 += 8) {
            uint32_t af[2][4], bf[4][2];
            #pragma unroll
            for (int mt = 0; mt < 2; mt++) {
                int row = warp * 32 + mt * 16 + lr;
                af[mt][0] = Ps[buf][k8 + lc][row];
                af[mt][1] = Ps[buf][k8 + lc][row + 8];
                af[mt][2] = Ps[buf][k8 + lc + 4][row];
                af[mt][3] = Ps[buf][k8 + lc + 4][row + 8];
            }
            #pragma unroll
            for (int nt = 0; nt < 4; nt++) {
                int col = nt * 8 + lr;
                bf[nt][0] = Vs[buf][k8 + lc][col];
                bf[nt][1] = Vs[buf][k8 + lc + 4][col];
            }
            #pragma unroll
            for (int mt = 0; mt < 2; mt++)
                #pragma unroll
                for (int nt = 0; nt < 4; nt++) mma_tf32(acc[mt][nt], af[mt], bf[nt]);
        }
        if (more) {
            int nb = buf ^ 1;
            #pragma unroll
            for (int q = 0; q < 16; q++) Ps[nb][q][tid] = f2tf32(pv[q]);
            Vs[nb][vr][vc + 0] = f2tf32(vv.x); Vs[nb][vr][vc + 1] = f2tf32(vv.y);
            Vs[nb][vr][vc + 2] = f2tf32(vv.z); Vs[nb][vr][vc + 3] = f2tf32(vv.w);
            __syncthreads();
        }
    }

    float* Pb = part + (size_t)split * (B_ * D_);
    #pragma unroll
    for (int mt = 0; mt < 2; mt++) {
        #pragma unroll
        for (int nt = 0; nt < 4; nt++) {
            int col = nt * 8 + 2 * lc;
            #pragma unroll
            for (int hrow = 0; hrow < 2; hrow++) {
                int row_g = qb * 128 + warp * 32 + mt * 16 + lr + hrow * 8;
                *(float2*)&Pb[(size_t)row_g * D_ + h * 32 + col]
                    = make_float2(acc[mt][nt][hrow * 2 + 0], acc[mt][nt][hrow * 2 + 1]);
            }
        }
    }
}

// ---------------- reduce AV partials, normalize, add self term -> ctx ---------
__global__ void reduce_ctx_kernel(const float* __restrict__ part, const float* __restrict__ pself,
                                  const float* __restrict__ sinv, const float* __restrict__ projsrc,
                                  float* __restrict__ ctx) {
    int b = blockIdx.x, d = threadIdx.x;
    int h = d >> 5;
    float s = 0.f;
    #pragma unroll
    for (int sp = 0; sp < NSPLIT_; sp++) s += part[(size_t)sp * (B_ * D_) + b * D_ + d];
    int ridx = h * B_ + b;
    s = s * sinv[ridx] + pself[ridx] * projsrc[b * 768 + 512 + d];
    ctx[b * D_ + d] = s;
}

// ---------------- LN with fused split-K reduce -------------------------------
__global__ void ln_split_kernel(const float* __restrict__ a, const float* __restrict__ part,
                                int nsplit, const float* __restrict__ bias,
                                const float* __restrict__ g, const float* __restrict__ be,
                                float* __restrict__ out) {
    int w = threadIdx.x >> 5, lane = threadIdx.x & 31;
    int row = blockIdx.x * 8 + w;
    size_t base = (size_t)row * D_ + lane * 8;
    float4 a0 = *(const float4*)(a + base);
    float4 a1 = *(const float4*)(a + base + 4);
    float x[8] = {a0.x, a0.y, a0.z, a0.w, a1.x, a1.y, a1.z, a1.w};
    for (int z = 0; z < nsplit; z++) {
        const float* pp = part + (size_t)z * (B_ * D_) + base;
        float4 p0 = *(const float4*)pp;
        float4 p1 = *(const float4*)(pp + 4);
        x[0]+=p0.x; x[1]+=p0.y; x[2]+=p0.z; x[3]+=p0.w;
        x[4]+=p1.x; x[5]+=p1.y; x[6]+=p1.z; x[7]+=p1.w;
    }
    float4 bb0 = *(const float4*)(bias + lane * 8);
    float4 bb1 = *(const float4*)(bias + lane * 8 + 4);
    x[0]+=bb0.x; x[1]+=bb0.y; x[2]+=bb0.z; x[3]+=bb0.w;
    x[4]+=bb1.x; x[5]+=bb1.y; x[6]+=bb1.z; x[7]+=bb1.w;

    float s = 0.f;
    #pragma unroll
    for (int j = 0; j < 8; j++) s += x[j];
    #pragma unroll
    for (int o = 16; o; o >>= 1) s += __shfl_xor_sync(0xFFFFFFFFu, s, o);
    float mean = s * (1.f / D_);
    float v = 0.f;
    #pragma unroll
    for (int j = 0; j < 8; j++) { float c = x[j] - mean; v += c * c; }
    #pragma unroll
    for (int o = 16; o; o >>= 1) v += __shfl_xor_sync(0xFFFFFFFFu, v, o);
    float rstd = rsqrtf(v * (1.f / D_) + 1e-5f);
    float4 g0 = *(const float4*)(g + lane * 8);
    float4 g1 = *(const float4*)(g + lane * 8 + 4);
    float4 e0 = *(const float4*)(be + lane * 8);
    float4 e1 = *(const float4*)(be + lane * 8 + 4);
    float gg[8] = {g0.x, g0.y, g0.z, g0.w, g1.x, g1.y, g1.z, g1.w};
    float ee[8] = {e0.x, e0.y, e0.z, e0.w, e1.x, e1.y, e1.z, e1.w};
    float o8[8];
    #pragma unroll
    for (int j = 0; j < 8; j++) o8[j] = (x[j] - mean) * rstd * gg[j] + ee[j];
    *(float4*)(out + base)     = make_float4(o8[0], o8[1], o8[2], o8[3]);
    *(float4*)(out + base + 4) = make_float4(o8[4], o8[5], o8[6], o8[7]);
}

// ---------------- scatter prep: flag from norms + ballot-scan prefix ----------
__global__ void scatter_prep_kernel(const int* __restrict__ ptrp) {
    __shared__ int wcnt[8];
    __shared__ int s_any[8];
    int t = threadIdx.x, w = t >> 5, lane = t & 31;
    // nonzero-memory flag: any mem row norm above the 1e-8 clamp
    int myany = 0;
    #pragma unroll
    for (int j = 0; j < 8; j++) myany |= (g_mem_norm[t + j * 256] > 1e-8f);
    unsigned am = __ballot_sync(0xFFFFFFFFu, myany);
    if (lane == 0) s_any[w] = (am != 0u);
    __syncthreads();
    int flag = 0;
    #pragma unroll
    for (int i = 0; i < 8; i++) flag |= s_any[i];

    float s = flag ? (1.0f - fdec(g_max_bits[t])) : 1.0f;
    int ptr = *ptrp;
    long long forced = (long long)M_ - (long long)ptr;
    int cond = (s > THR_) || ((long long)t < forced);
    unsigned mask = __ballot_sync(0xFFFFFFFFu, cond);
    int lpref = __popc(mask & ((1u << lane) - 1u));
    if (lane == 31) wcnt[w] = lpref + cond;
    #pragma unroll
    for (int j = 0; j < 8; j++) g_row_src[t + j * 256] = -1;
    __syncthreads();
    int wbase = 0;
    #pragma unroll
    for (int i = 0; i < 8; i++) { if (i < w) wbase += wcnt[i]; }
    g_upd_s[t] = s;
    if (cond) {
        long long p = (long long)ptr + (wbase + lpref);
        int idx = (int)(p % M_); if (idx < 0) idx += M_;
        g_row_src[idx] = t;
    }
}

// ---------------- full-coverage memory update --------------------------------
__global__ void update_kernel(const float* __restrict__ mem, const float* __restrict__ mom,
                              const float* __restrict__ scores,
                              float* __restrict__ out_mem, float* __restrict__ out_mom,
                              float* __restrict__ out_sc) {
    int row = blockIdx.x, t = threadIdx.x;
    int i = g_row_src[row];
    size_t o = (size_t)row * D_ + t;
    float mval = mem[o], mo = mom[o];
    if (i >= 0) {
        float diff = g_h[i * D_ + t] - mval;
        float nm = MOM_ * mo + (1.0f - MOM_) * diff;
        out_mem[o] = mval + LR_ * nm;
        out_mom[o] = nm;
    } else {
        out_mem[o] = mval;
        out_mom[o] = mo;
    }
    if (t == 0) out_sc[row] = (i >= 0) ? g_upd_s[i] : scores[row];
}

// ---------------- launch -----------------------------------------------------
extern "C" void kernel_launch(void* const* d_in, const int* in_sizes, int n_in,
                              void* d_out, int out_size) {
    const float* src       = (const float*)d_in[0];
    const float* memory    = (const float*)d_in[1];
    const float* momentum  = (const float*)d_in[2];
    const float* scores    = (const float*)d_in[3];
    const float* in_proj_w = (const float*)d_in[4];
    const float* in_proj_b = (const float*)d_in[5];
    const float* out_w     = (const float*)d_in[6];
    const float* out_b     = (const float*)d_in[7];
    const float* w1        = (const float*)d_in[8];
    const float* b1        = (const float*)d_in[9];
    const float* w2        = (const float*)d_in[10];
    const float* b2        = (const float*)d_in[11];
    const float* g1        = (const float*)d_in[12];
    const float* be1       = (const float*)d_in[13];
    const float* g2        = (const float*)d_in[14];
    const float* be2       = (const float*)d_in[15];
    const int*   ptr       = (const int*)d_in[16];

    float* out     = (float*)d_out;
    float* out_mem = out + B_ * D_;
    float* out_mom = out_mem + M_ * D_;
    float* out_sc  = out_mom + M_ * D_;

    float *proj_p, *kv_p, *pself_p, *sinv_p, *part_p, *ap_p, *fp_p, *ctx_p, *h_p, *hid_p;
    __nv_bfloat16* log_p;
    cudaGetSymbolAddress((void**)&proj_p,  g_proj_src);
    cudaGetSymbolAddress((void**)&kv_p,    g_kv_mem);
    cudaGetSymbolAddress((void**)&log_p,   g_logits);
    cudaGetSymbolAddress((void**)&pself_p, g_pself);
    cudaGetSymbolAddress((void**)&sinv_p,  g_sinv);
    cudaGetSymbolAddress((void**)&part_p,  g_ctx_part);
    cudaGetSymbolAddress((void**)&ap_p,    g_attn_part);
    cudaGetSymbolAddress((void**)&fp_p,    g_ff_part);
    cudaGetSymbolAddress((void**)&ctx_p,   g_ctx);
    cudaGetSymbolAddress((void**)&h_p,     g_h);
    cudaGetSymbolAddress((void**)&hid_p,   g_hidden);

    static cudaStream_t s1 = nullptr, s2 = nullptr;
    static cudaEvent_t eFork = nullptr, eKV = nullptr, eS2 = nullptr,
                       eLN1 = nullptr, eUpd = nullptr, eLog = nullptr, ePS = nullptr;
    if (!s1) {
        cudaStreamCreateWithFlags(&s1, cudaStreamNonBlocking);
        cudaStreamCreateWithFlags(&s2, cudaStreamNonBlocking);
        cudaEventCreateWithFlags(&eFork, cudaEventDisableTiming);
        cudaEventCreateWithFlags(&eKV,   cudaEventDisableTiming);
        cudaEventCreateWithFlags(&eS2,   cudaEventDisableTiming);
        cudaEventCreateWithFlags(&eLN1,  cudaEventDisableTiming);
        cudaEventCreateWithFlags(&eUpd,  cudaEventDisableTiming);
        cudaEventCreateWithFlags(&eLog,  cudaEventDisableTiming);
        cudaEventCreateWithFlags(&ePS,   cudaEventDisableTiming);
    }

    // ---- fork ----
    cudaEventRecord(eFork, 0);
    cudaStreamWaitEvent(s1, eFork, 0);
    cudaStreamWaitEvent(s2, eFork, 0);

    // S1: memory k|v projection [2048,512] (tf32)
    tmma64<0><<<dim3(8, 32, 1), 128, 0, s1>>>(memory, in_proj_w + D_ * D_, in_proj_b + D_, kv_p,
                                              256, 256, 256, 512, 0, 0, 0);
    cudaEventRecord(eKV, s1);

    // S2: norms (+max_bits init) -> cosine (tf32, MODE 4) -> scatter prep
    norms_kernel<<<(B_ + M_ + 7) / 8, dim3(32, 8), 0, s2>>>(src, memory);
    tmma64<4><<<dim3(32, 4, 1), 128, 0, s2>>>(src, memory, nullptr, nullptr,
                                              256, 256, 256, 0, 0, 0, 0);
    scatter_prep_kernel<<<1, 256, 0, s2>>>(ptr);
    cudaEventRecord(eS2, s2);

    // S0: src projections [256,768] (tf32)
    tmma64<0><<<dim3(12, 4, 1), 128>>>(src, in_proj_w, in_proj_b, proj_p,
                                       256, 256, 256, 768, 0, 0, 0);

    // S0: logits GEMM with exp epilogue (bf16 unnormalized exps + psum)
    cudaStreamWaitEvent(0, eKV, 0);
    tmma64<5><<<dim3(32, 4, H_), 128>>>(proj_p, kv_p, nullptr, (float*)log_p,
                                        32, 768, 512, 2048, 32, 32, B_ * M_);
    cudaEventRecord(eLog, 0);

    // S2 (concurrent with AV): pself/sinv reduction
    cudaStreamWaitEvent(s2, eLog, 0);
    pself_kernel<<<B_ * H_ / 8, 256, 0, s2>>>(proj_p, sinv_p, pself_p);
    cudaEventRecord(ePS, s2);

    // S0: AV directly on unnormalized exps
    av_tmma<<<dim3(2, NSPLIT_, H_), 128>>>(log_p, kv_p, part_p);
    cudaStreamWaitEvent(0, ePS, 0);
    reduce_ctx_kernel<<<B_, 256>>>(part_p, pself_p, sinv_p, proj_p, ctx_p);

    // out-proj split-K x4 (tf32) -> partials; LN1 fuses reduce + bias
    tmma64<0><<<dim3(4, 4, 4), 128>>>(ctx_p, out_w, nullptr, ap_p,
                                      64, 256, 256, 256, 64, 64, B_ * D_);
    ln_split_kernel<<<B_ / 8, 256>>>(src, ap_p, 4, out_b, g1, be1, h_p);
    cudaEventRecord(eLN1, 0);

    // S1: memory update path (needs h + scatter map), overlaps FFN
    cudaStreamWaitEvent(s1, eLN1, 0);
    cudaStreamWaitEvent(s1, eS2, 0);
    update_kernel<<<M_, 256, 0, s1>>>(memory, momentum, scores, out_mem, out_mom, out_sc);
    cudaEventRecord(eUpd, s1);

    // S0: FFN1 (tf32 relu+bias), FFN2 split-K x16 (tf32); LN2 fuses reduce
    tmma64<2><<<dim3(16, 4, 1), 128>>>(h_p, w1, b1, hid_p,
                                       256, 256, 256, 1024, 0, 0, 0);
    tmma64<0><<<dim3(4, 4, FSPLIT_), 128>>>(hid_p, w2, nullptr, fp_p,
                                            1024 / FSPLIT_, 1024, 1024, 256,
                                            1024 / FSPLIT_, 1024 / FSPLIT_, B_ * D_);
    ln_split_kernel<<<B_ / 8, 256>>>(h_p, fp_p, FSPLIT_, b2, g2, be2, out);

    // ---- join ----
    cudaStreamWaitEvent(0, eUpd, 0);
}